// round 1
// baseline (speedup 1.0000x reference)
#include <cuda_runtime.h>
#include <math.h>

#define IN_DIM 1024
#define ED 256
#define NE 512
#define TM 64
#define BK 16
#define NTHREADS 256
#define XT_PITCH 66
#define WT_PITCH 260
#define PS_PITCH 260

typedef unsigned long long u64;

// normalized centers, transposed to [k][e] = [256][512]
__device__ float g_cnT[ED * NE];

static __device__ __forceinline__ u64 pack2(float lo, float hi) {
    u64 r; asm("mov.b64 %0, {%1, %2};" : "=l"(r) : "f"(lo), "f"(hi)); return r;
}
static __device__ __forceinline__ void unpack2(u64 v, float& lo, float& hi) {
    asm("mov.b64 {%0, %1}, %2;" : "=f"(lo), "=f"(hi) : "l"(v));
}
static __device__ __forceinline__ void ffma2(u64& d, u64 a, u64 b) {
    asm("fma.rn.f32x2 %0, %1, %2, %0;" : "+l"(d) : "l"(a), "l"(b));
}

static __device__ __forceinline__ void upd(float v, int i,
                                           float& v1, int& i1, float& v2, int& i2) {
    if (v > v1 || (v == v1 && i < i1)) { v2 = v1; i2 = i1; v1 = v; i1 = i; }
    else if (v > v2 || (v == v2 && i < i2)) { v2 = v; i2 = i; }
}

__global__ void cnorm_kernel(const float* __restrict__ centers) {
    __shared__ float ws[8];
    int e = blockIdx.x, t = threadIdx.x;
    float v = centers[e * ED + t];
    float s = v * v;
    #pragma unroll
    for (int o = 16; o; o >>= 1) s += __shfl_xor_sync(0xffffffffu, s, o);
    if ((t & 31) == 0) ws[t >> 5] = s;
    __syncthreads();
    float tot = 0.f;
    #pragma unroll
    for (int i = 0; i < 8; ++i) tot += ws[i];
    float norm = fmaxf(sqrtf(tot), 1e-12f);
    g_cnT[t * NE + e] = v / norm;
}

__global__ __launch_bounds__(NTHREADS, 1)
void router_kernel(const float* __restrict__ x, const float* __restrict__ W,
                   const float* __restrict__ bias, float* __restrict__ out, int ntok) {
    extern __shared__ float smem[];
    float* xT = smem;                       // [BK][XT_PITCH] k-major x tile
    float* wT = smem + BK * XT_PITCH;       // [BK][WT_PITCH] k-major W / centers tile
    float* Ps = wT + BK * WT_PITCH;         // [TM][PS_PITCH] projection (with bias)

    const int tid = threadIdx.x;
    const int tn = tid & 31, tm = tid >> 5;
    const int t0 = blockIdx.x * TM;
    const int mb = tm * 8;
    const int nA = tn * 4, nB = 128 + tn * 4;

    u64 acc[4][8];
    #pragma unroll
    for (int p = 0; p < 4; ++p)
        #pragma unroll
        for (int j = 0; j < 8; ++j) acc[p][j] = 0ull;

    // ---------------- GEMM1: P = x @ W^T ----------------
    const float* xptr = x + (size_t)(t0 + (tid >> 2)) * IN_DIM + (tid & 3) * 4;
    const float* wptr = W + (size_t)tid * IN_DIM;

    float4 xs  = *(const float4*)xptr;
    float4 ws0 = *(const float4*)(wptr + 0);
    float4 ws1 = *(const float4*)(wptr + 4);
    float4 ws2 = *(const float4*)(wptr + 8);
    float4 ws3 = *(const float4*)(wptr + 12);

    const int mrow = tid >> 2, kq = tid & 3;

    for (int kt = 0; kt < IN_DIM / BK; ++kt) {
        // store staged tile (transposed to k-major)
        xT[(kq * 4 + 0) * XT_PITCH + mrow] = xs.x;
        xT[(kq * 4 + 1) * XT_PITCH + mrow] = xs.y;
        xT[(kq * 4 + 2) * XT_PITCH + mrow] = xs.z;
        xT[(kq * 4 + 3) * XT_PITCH + mrow] = xs.w;
        wT[ 0 * WT_PITCH + tid] = ws0.x;  wT[ 1 * WT_PITCH + tid] = ws0.y;
        wT[ 2 * WT_PITCH + tid] = ws0.z;  wT[ 3 * WT_PITCH + tid] = ws0.w;
        wT[ 4 * WT_PITCH + tid] = ws1.x;  wT[ 5 * WT_PITCH + tid] = ws1.y;
        wT[ 6 * WT_PITCH + tid] = ws1.z;  wT[ 7 * WT_PITCH + tid] = ws1.w;
        wT[ 8 * WT_PITCH + tid] = ws2.x;  wT[ 9 * WT_PITCH + tid] = ws2.y;
        wT[10 * WT_PITCH + tid] = ws2.z;  wT[11 * WT_PITCH + tid] = ws2.w;
        wT[12 * WT_PITCH + tid] = ws3.x;  wT[13 * WT_PITCH + tid] = ws3.y;
        wT[14 * WT_PITCH + tid] = ws3.z;  wT[15 * WT_PITCH + tid] = ws3.w;
        __syncthreads();
        if (kt + 1 < IN_DIM / BK) {
            const float* xn = xptr + (kt + 1) * BK;
            const float* wn = wptr + (kt + 1) * BK;
            xs  = *(const float4*)xn;
            ws0 = *(const float4*)(wn + 0);
            ws1 = *(const float4*)(wn + 4);
            ws2 = *(const float4*)(wn + 8);
            ws3 = *(const float4*)(wn + 12);
        }
        #pragma unroll
        for (int k = 0; k < BK; ++k) {
            u64 a0 = *(const u64*)(xT + k * XT_PITCH + mb + 0);
            u64 a1 = *(const u64*)(xT + k * XT_PITCH + mb + 2);
            u64 a2 = *(const u64*)(xT + k * XT_PITCH + mb + 4);
            u64 a3 = *(const u64*)(xT + k * XT_PITCH + mb + 6);
            float4 b0 = *(const float4*)(wT + k * WT_PITCH + nA);
            float4 b1 = *(const float4*)(wT + k * WT_PITCH + nB);
            u64 bb[8];
            bb[0] = pack2(b0.x, b0.x); bb[1] = pack2(b0.y, b0.y);
            bb[2] = pack2(b0.z, b0.z); bb[3] = pack2(b0.w, b0.w);
            bb[4] = pack2(b1.x, b1.x); bb[5] = pack2(b1.y, b1.y);
            bb[6] = pack2(b1.z, b1.z); bb[7] = pack2(b1.w, b1.w);
            #pragma unroll
            for (int j = 0; j < 8; ++j) {
                ffma2(acc[0][j], a0, bb[j]);
                ffma2(acc[1][j], a1, bb[j]);
                ffma2(acc[2][j], a2, bb[j]);
                ffma2(acc[3][j], a3, bb[j]);
            }
        }
        __syncthreads();
    }

    // ---------------- epilogue: bias, sumsq, stash P ----------------
    float bj[8];
    #pragma unroll
    for (int j = 0; j < 4; ++j) { bj[j] = bias[nA + j]; bj[4 + j] = bias[nB + j]; }
    float sq[8];
    #pragma unroll
    for (int r = 0; r < 8; ++r) sq[r] = 0.f;

    #pragma unroll
    for (int p = 0; p < 4; ++p) {
        float lo[8], hi[8];
        #pragma unroll
        for (int j = 0; j < 8; ++j) {
            float l, h; unpack2(acc[p][j], l, h);
            l += bj[j]; h += bj[j];
            sq[2 * p]     += l * l;
            sq[2 * p + 1] += h * h;
            lo[j] = l; hi[j] = h;
        }
        *(float4*)(Ps + (mb + 2 * p) * PS_PITCH + nA)     = make_float4(lo[0], lo[1], lo[2], lo[3]);
        *(float4*)(Ps + (mb + 2 * p) * PS_PITCH + nB)     = make_float4(lo[4], lo[5], lo[6], lo[7]);
        *(float4*)(Ps + (mb + 2 * p + 1) * PS_PITCH + nA) = make_float4(hi[0], hi[1], hi[2], hi[3]);
        *(float4*)(Ps + (mb + 2 * p + 1) * PS_PITCH + nB) = make_float4(hi[4], hi[5], hi[6], hi[7]);
    }
    #pragma unroll
    for (int r = 0; r < 8; ++r)
        #pragma unroll
        for (int o = 16; o; o >>= 1) sq[r] += __shfl_xor_sync(0xffffffffu, sq[r], o);
    __syncthreads();

    // ---------------- GEMM2: S = P @ Cn^T, fused top-2 ----------------
    float v1[8], v2[8]; int i1[8], i2[8];
    #pragma unroll
    for (int r = 0; r < 8; ++r) { v1[r] = -INFINITY; v2[r] = -INFINITY; i1[r] = 0; i2[r] = 0; }

    const int ckr = tid >> 4;            // 0..15 : k row within tile
    const int ccol = (tid & 15) * 16;    // 0..240 : n col

    for (int ch = 0; ch < 2; ++ch) {
        #pragma unroll
        for (int p = 0; p < 4; ++p)
            #pragma unroll
            for (int j = 0; j < 8; ++j) acc[p][j] = 0ull;

        const float* cptr = g_cnT + (size_t)ckr * NE + ch * 256 + ccol;
        float4 cs0 = *(const float4*)(cptr + 0);
        float4 cs1 = *(const float4*)(cptr + 4);
        float4 cs2 = *(const float4*)(cptr + 8);
        float4 cs3 = *(const float4*)(cptr + 12);

        for (int kt = 0; kt < ED / BK; ++kt) {
            *(float4*)(wT + ckr * WT_PITCH + ccol + 0)  = cs0;
            *(float4*)(wT + ckr * WT_PITCH + ccol + 4)  = cs1;
            *(float4*)(wT + ckr * WT_PITCH + ccol + 8)  = cs2;
            *(float4*)(wT + ckr * WT_PITCH + ccol + 12) = cs3;
            __syncthreads();
            if (kt + 1 < ED / BK) {
                const float* cn = cptr + (size_t)(kt + 1) * BK * NE;
                cs0 = *(const float4*)(cn + 0);
                cs1 = *(const float4*)(cn + 4);
                cs2 = *(const float4*)(cn + 8);
                cs3 = *(const float4*)(cn + 12);
            }
            #pragma unroll
            for (int k = 0; k < BK; ++k) {
                u64 a[4];
                #pragma unroll
                for (int p = 0; p < 4; ++p) {
                    float l = Ps[(mb + 2 * p) * PS_PITCH + kt * BK + k];
                    float h = Ps[(mb + 2 * p + 1) * PS_PITCH + kt * BK + k];
                    a[p] = pack2(l, h);
                }
                float4 b0 = *(const float4*)(wT + k * WT_PITCH + nA);
                float4 b1 = *(const float4*)(wT + k * WT_PITCH + nB);
                u64 bb[8];
                bb[0] = pack2(b0.x, b0.x); bb[1] = pack2(b0.y, b0.y);
                bb[2] = pack2(b0.z, b0.z); bb[3] = pack2(b0.w, b0.w);
                bb[4] = pack2(b1.x, b1.x); bb[5] = pack2(b1.y, b1.y);
                bb[6] = pack2(b1.z, b1.z); bb[7] = pack2(b1.w, b1.w);
                #pragma unroll
                for (int j = 0; j < 8; ++j) {
                    ffma2(acc[0][j], a[0], bb[j]);
                    ffma2(acc[1][j], a[1], bb[j]);
                    ffma2(acc[2][j], a[2], bb[j]);
                    ffma2(acc[3][j], a[3], bb[j]);
                }
            }
            __syncthreads();
        }
        // fold this chunk of 256 experts into running per-lane top-2
        #pragma unroll
        for (int p = 0; p < 4; ++p) {
            #pragma unroll
            for (int j = 0; j < 8; ++j) {
                float l, h; unpack2(acc[p][j], l, h);
                int gi = ch * 256 + ((j < 4) ? (nA + j) : (nB + j - 4));
                upd(l, gi, v1[2 * p],     i1[2 * p],     v2[2 * p],     i2[2 * p]);
                upd(h, gi, v1[2 * p + 1], i1[2 * p + 1], v2[2 * p + 1], i2[2 * p + 1]);
            }
        }
    }

    // warp butterfly merge of top-2 across the 32 lanes (full 512 experts)
    #pragma unroll
    for (int r = 0; r < 8; ++r) {
        #pragma unroll
        for (int o = 16; o; o >>= 1) {
            float o1 = __shfl_xor_sync(0xffffffffu, v1[r], o);
            int  oi1 = __shfl_xor_sync(0xffffffffu, i1[r], o);
            float o2 = __shfl_xor_sync(0xffffffffu, v2[r], o);
            int  oi2 = __shfl_xor_sync(0xffffffffu, i2[r], o);
            upd(o1, oi1, v1[r], i1[r], v2[r], i2[r]);
            upd(o2, oi2, v1[r], i1[r], v2[r], i2[r]);
        }
    }

    if (tn == 0) {
        float* oi = out + 2 * (size_t)ntok;
        #pragma unroll
        for (int r = 0; r < 8; ++r) {
            int token = t0 + mb + r;
            float inv = 1.f / fmaxf(sqrtf(sq[r]), 1e-12f);
            float V1 = v1[r] * inv, V2 = v2[r] * inv;
            float e2 = expf(V2 - V1);
            float den = 1.f + e2;
            out[2 * token]     = 1.f / den;
            out[2 * token + 1] = e2 / den;
            oi[2 * token]      = (float)i1[r];
            oi[2 * token + 1]  = (float)i2[r];
        }
    }
}

extern "C" void kernel_launch(void* const* d_in, const int* in_sizes, int n_in,
                              void* d_out, int out_size) {
    const float* x = (const float*)d_in[0];
    const float* W = (const float*)d_in[1];
    const float* b = (const float*)d_in[2];
    const float* c = (const float*)d_in[3];
    int ntok = in_sizes[0] / IN_DIM;   // 64 * 2048 = 131072

    cnorm_kernel<<<NE, ED>>>(c);

    int smem_bytes = (BK * XT_PITCH + BK * WT_PITCH + TM * PS_PITCH) * (int)sizeof(float);
    cudaFuncSetAttribute(router_kernel, cudaFuncAttributeMaxDynamicSharedMemorySize, smem_bytes);
    router_kernel<<<ntok / TM, NTHREADS, smem_bytes>>>(x, W, b, (float*)d_out, ntok);
}